// round 1
// baseline (speedup 1.0000x reference)
#include <cuda_runtime.h>
#include <math.h>

// ---------------- problem constants ----------------
#define BS    128
#define CH    16
#define T     12288
#define C1    32
#define T1    3072        // after meanpool4
#define C2    64
#define T2    768         // after meanpool4
#define C3    8
#define LATENT 6144       // 8*768
#define NMW   96          // mini windows
#define TOPK  5
#define RED   6
#define WLEN  2048        // mini-window length (16*12288/96)
#define GKS   15
#define GOC   64
#define LG    2034        // 2048-15+1
#define LGP   508         // 2034//4
#define E2OC  128
#define E2L   502         // 508-7+1
#define E2P   125         // 502//4
#define E3L   119         // 125-7+1
#define NCLS  5
#define NSPLIT 16         // D-split for linear1 partials

// ---------------- scratch (device globals; no allocs allowed) ----------------
__device__ float g_h1[BS * C1 * T1];        // 50.3 MB
__device__ float g_h2[BS * C2 * T2];        // 25.2 MB
__device__ float g_h3[BS * LATENT];         // 3.1 MB
__device__ float g_upart[NSPLIT][BS * NMW]; // 0.79 MB
__device__ int   g_idx[BS * TOPK];
__device__ float g_n0[BS];
__device__ float g_z1[BS * GOC * LGP];      // 16.6 MB
__device__ float g_z2[BS * E2OC * E2P];     // 8.2 MB
__device__ float g_S[BS * E2OC * 7];
__device__ float g_feat[BS * E2OC];

__device__ __forceinline__ float leaky(float z) { return z >= 0.f ? z : 0.01f * z; }

// ================= K1: conv1(16->32,ks7,reflect-same) + leaky + meanpool4 =================
// grid (48, BS) : 64 pooled outputs per block (256 raw). block 256 = 32 oc x 8 sub.
__global__ void k_conv1(const float* __restrict__ x, const float* __restrict__ w,
                        const float* __restrict__ bb) {
    const int b = blockIdx.y, chunk = blockIdx.x;
    __shared__ float sw[C1 * 113];      // per-oc stride 113 (odd -> conflict free)
    __shared__ float sx[CH][262];
    const int tid = threadIdx.x;
    for (int i = tid; i < C1 * CH * 7; i += 256) {
        int o = i / 112, r = i % 112;
        sw[o * 113 + r] = w[i];
    }
    const int t0 = chunk * 256 - 3;
    for (int i = tid; i < CH * 262; i += 256) {
        int ic = i / 262, p = i % 262;
        int t = t0 + p;
        if (t < 0) t = -t;
        if (t >= T) t = 2 * T - 2 - t;
        sx[ic][p] = x[(b * CH + ic) * T + t];
    }
    __syncthreads();
    const int o = tid & 31, sub = tid >> 5;
    const float bias = bb[o];
    float acc[8][4];
#pragma unroll
    for (int p = 0; p < 8; p++)
#pragma unroll
        for (int j = 0; j < 4; j++) acc[p][j] = bias;
    for (int ic = 0; ic < CH; ic++) {
        float wr[7];
#pragma unroll
        for (int k = 0; k < 7; k++) wr[k] = sw[o * 113 + ic * 7 + k];
#pragma unroll
        for (int p = 0; p < 8; p++) {
            const int base = (sub * 8 + p) * 4;
            float v[10];
#pragma unroll
            for (int m = 0; m < 10; m++) v[m] = sx[ic][base + m];
#pragma unroll
            for (int j = 0; j < 4; j++) {
                float s = 0.f;
#pragma unroll
                for (int k = 0; k < 7; k++) s += v[j + k] * wr[k];
                acc[p][j] += s;
            }
        }
    }
#pragma unroll
    for (int p = 0; p < 8; p++) {
        float m = 0.f;
#pragma unroll
        for (int j = 0; j < 4; j++) m += leaky(acc[p][j]);
        g_h1[(b * C1 + o) * T1 + chunk * 64 + sub * 8 + p] = m * 0.25f;
    }
}

// ================= K2: conv2(32->64,ks7,reflect-same) + leaky + meanpool4 =================
// grid (24*2, BS): chunk = bx>>1 (32 pooled), ohalf = bx&1. block 256 = 32 ocl x 8 sub.
__global__ void k_conv2(const float* __restrict__ w, const float* __restrict__ bb) {
    const int b = blockIdx.y;
    const int chunk = blockIdx.x >> 1, ohalf = blockIdx.x & 1;
    __shared__ float sw[32 * 225];      // 32 local oc, stride 225 (32*7=224)
    __shared__ float sx[32][134];
    const int tid = threadIdx.x;
    for (int i = tid; i < 32 * 32 * 7; i += 256) {
        int ol = i / 224, r = i % 224;
        sw[ol * 225 + r] = w[(ohalf * 32 + ol) * 224 + r];
    }
    const int t0 = chunk * 128 - 3;
    for (int i = tid; i < 32 * 134; i += 256) {
        int ic = i / 134, p = i % 134;
        int t = t0 + p;
        if (t < 0) t = -t;
        if (t >= T1) t = 2 * T1 - 2 - t;
        sx[ic][p] = g_h1[(b * C1 + ic) * T1 + t];
    }
    __syncthreads();
    const int ol = tid & 31, sub = tid >> 5;
    const int oc = ohalf * 32 + ol;
    const float bias = bb[oc];
    float acc[4][4];
#pragma unroll
    for (int p = 0; p < 4; p++)
#pragma unroll
        for (int j = 0; j < 4; j++) acc[p][j] = bias;
    for (int ic = 0; ic < 32; ic++) {
        float wr[7];
#pragma unroll
        for (int k = 0; k < 7; k++) wr[k] = sw[ol * 225 + ic * 7 + k];
#pragma unroll
        for (int p = 0; p < 4; p++) {
            const int base = (sub * 4 + p) * 4;
            float v[10];
#pragma unroll
            for (int m = 0; m < 10; m++) v[m] = sx[ic][base + m];
#pragma unroll
            for (int j = 0; j < 4; j++) {
                float s = 0.f;
#pragma unroll
                for (int k = 0; k < 7; k++) s += v[j + k] * wr[k];
                acc[p][j] += s;
            }
        }
    }
#pragma unroll
    for (int p = 0; p < 4; p++) {
        float m = 0.f;
#pragma unroll
        for (int j = 0; j < 4; j++) m += leaky(acc[p][j]);
        g_h2[(b * C2 + oc) * T2 + chunk * 32 + sub * 4 + p] = m * 0.25f;
    }
}

// ================= K3: conv3(64->8,ks7,reflect-same) + tanh -> flatten =================
// grid (12, BS): 64 t per block. block 256 = 32 tl x 8 oc; 2 t per thread.
__global__ void k_conv3(const float* __restrict__ w, const float* __restrict__ bb) {
    const int b = blockIdx.y, chunk = blockIdx.x;
    __shared__ float sw[C3 * 449];  // per-oc stride 449 (64*7=448)
    __shared__ float sx[C2][70];
    const int tid = threadIdx.x;
    for (int i = tid; i < C3 * C2 * 7; i += 256) {
        int o = i / 448, r = i % 448;
        sw[o * 449 + r] = w[i];
    }
    const int t0 = chunk * 64 - 3;
    for (int i = tid; i < C2 * 70; i += 256) {
        int ic = i / 70, p = i % 70;
        int t = t0 + p;
        if (t < 0) t = -t;
        if (t >= T2) t = 2 * T2 - 2 - t;
        sx[ic][p] = g_h2[(b * C2 + ic) * T2 + t];
    }
    __syncthreads();
    const int o = tid >> 5, tl = tid & 31;
    float a0 = bb[o], a1 = bb[o];
    for (int ic = 0; ic < C2; ic++) {
#pragma unroll
        for (int k = 0; k < 7; k++) {
            float wv = sw[o * 449 + ic * 7 + k];
            a0 += sx[ic][tl + k] * wv;
            a1 += sx[ic][tl + 32 + k] * wv;
        }
    }
    const int tg = chunk * 64;
    g_h3[b * LATENT + o * T2 + tg + tl]      = tanhf(a0);
    g_h3[b * LATENT + o * T2 + tg + tl + 32] = tanhf(a1);
}

// ================= K4a: u_partial = h3 @ hl1^T  (split over D) =================
// grid (4 btiles, NSPLIT). block 256, each thread 12 (b,n) pairs.
__global__ void k_lin1(const float* __restrict__ hl1) {
    const int btile = blockIdx.x, ds = blockIdx.y;
    __shared__ float sh[32 * 65];
    __shared__ float swt[96 * 65];
    const int tid = threadIdx.x;
    float acc[12];
#pragma unroll
    for (int r = 0; r < 12; r++) acc[r] = 0.f;
    const int dbase = ds * (LATENT / NSPLIT);  // 384-wide stripe
    for (int sc = 0; sc < 6; sc++) {
        const int dd0 = dbase + sc * 64;
        __syncthreads();
        for (int i = tid; i < 32 * 64; i += 256) {
            int bl = i >> 6, d = i & 63;
            sh[bl * 65 + d] = g_h3[(btile * 32 + bl) * LATENT + dd0 + d];
        }
        for (int i = tid; i < 96 * 64; i += 256) {
            int n = i >> 6, d = i & 63;
            swt[n * 65 + d] = hl1[n * LATENT + dd0 + d];
        }
        __syncthreads();
#pragma unroll
        for (int r = 0; r < 12; r++) {
            const int p = tid + 256 * r;
            const int bl = p / 96, n = p % 96;
            float a = 0.f;
#pragma unroll 8
            for (int d = 0; d < 64; d++) a += sh[bl * 65 + d] * swt[n * 65 + d];
            acc[r] += a;
        }
    }
#pragma unroll
    for (int r = 0; r < 12; r++) {
        const int p = tid + 256 * r;
        const int bl = p / 96, n = p % 96;
        g_upart[ds][(btile * 32 + bl) * 96 + n] = acc[r];
    }
}

// ================= K4b: u-reduce + leaky + @hl2^T + top-k =================
__global__ void k_logits_topk(const float* __restrict__ hl2) {
    const int b = blockIdx.x, tid = threadIdx.x;
    __shared__ float su[96];
    __shared__ float slog[96];
    if (tid < 96) {
        float u = 0.f;
#pragma unroll
        for (int ds = 0; ds < NSPLIT; ds++) u += g_upart[ds][b * 96 + tid];
        su[tid] = leaky(u);
    }
    __syncthreads();
    if (tid < 96) {
        float lg = 0.f;
        for (int n = 0; n < 96; n++) lg += su[n] * hl2[tid * 96 + n];
        slog[tid] = lg;
    }
    __syncthreads();
    if (tid == 0) {
        int n0 = 0;
        for (int k = 0; k < TOPK; k++) {
            float best = -INFINITY;
            int bi = 0;
            for (int n = 0; n < 96; n++) {
                if (slog[n] > best) { best = slog[n]; bi = n; }
            }
            slog[bi] = -INFINITY;
            g_idx[b * TOPK + k] = bi;
            if (bi / RED == 0) n0++;
        }
        g_n0[b] = (float)n0;
    }
}

// ================= K5: grouped conv (5 windows, ks15, 64oc) + bias + leaky + maxpool4 =====
// grid (32, BS): 16 pooled per block. block 256 = 64 oc x 4 ty.
__global__ void k_gconv(const float* __restrict__ x, const float* __restrict__ gw,
                        const float* __restrict__ gb0) {
    const int b = blockIdx.y, chunk = blockIdx.x;
    __shared__ float sgw[TOPK * GOC * GKS];  // [k][o][s] stride 15 (odd -> ok)
    __shared__ float sx[TOPK][80];
    __shared__ int sidx[TOPK];
    const int tid = threadIdx.x;
    if (tid < TOPK) sidx[tid] = g_idx[b * TOPK + tid];
    __syncthreads();
    for (int i = tid; i < TOPK * GOC * GKS; i += 256) {
        int k = i / (GOC * GKS), r = i % (GOC * GKS);
        sgw[i] = gw[(sidx[k] / RED) * (GOC * GKS) + r];
    }
    for (int i = tid; i < TOPK * 80; i += 256) {
        int k = i / 80, p = i % 80;
        int pos = chunk * 64 + p;
        float v = 0.f;
        if (pos < WLEN) v = x[b * (CH * T) + sidx[k] * WLEN + pos];
        sx[k][p] = v;
    }
    __syncthreads();
    const int o = tid & 63, ty = tid >> 6;
    const float biasv = g_n0[b] * gb0[o];
#pragma unroll
    for (int rep = 0; rep < 4; rep++) {
        const int lpl = ty + 4 * rep;           // 0..15
        const int lp = chunk * 16 + lpl;
        float accj[4];
#pragma unroll
        for (int j = 0; j < 4; j++) accj[j] = biasv;
        for (int k = 0; k < TOPK; k++) {
            float wv[GKS];
#pragma unroll
            for (int s = 0; s < GKS; s++) wv[s] = sgw[k * (GOC * GKS) + o * GKS + s];
            const int r0 = lpl * 4;
            float v[18];
#pragma unroll
            for (int m = 0; m < 18; m++) v[m] = sx[k][r0 + m];
#pragma unroll
            for (int j = 0; j < 4; j++) {
                float s = 0.f;
#pragma unroll
                for (int q = 0; q < GKS; q++) s += v[j + q] * wv[q];
                accj[j] += s;
            }
        }
        if (lp < LGP) {
            float mx = -INFINITY;
#pragma unroll
            for (int j = 0; j < 4; j++) mx = fmaxf(mx, leaky(accj[j]));
            g_z1[(b * GOC + o) * LGP + lp] = mx;
        }
    }
}

// ================= K6: ew2 conv(64->128,ks7) + bias + leaky + maxpool4 =================
// grid (10, BS): 13 pooled per block. block 256 = 128 oc x 2 ty. ic staged in chunks of 8.
__global__ void k_econv2(const float* __restrict__ w, const float* __restrict__ bb) {
    const int b = blockIdx.y, chunk = blockIdx.x;
    __shared__ float sw[E2OC * 57];  // 8 ic * 7 = 56, stride 57
    __shared__ float sx[GOC][58];
    const int tid = threadIdx.x;
    const int rbase = chunk * 52;
    for (int i = tid; i < GOC * 58; i += 256) {
        int ic = i / 58, p = i % 58;
        int idx = rbase + p;
        sx[ic][p] = (idx < LGP) ? g_z1[(b * GOC + ic) * LGP + idx] : 0.f;
    }
    const int oc = tid & 127, ty = tid >> 7;
    float acc[7][4];
    const float bias = bb[oc];
#pragma unroll
    for (int m = 0; m < 7; m++)
#pragma unroll
        for (int j = 0; j < 4; j++) acc[m][j] = bias;
    for (int icc = 0; icc < 8; icc++) {
        __syncthreads();
        for (int i = tid; i < E2OC * 56; i += 256) {
            int o = i / 56, r = i % 56;
            int icl = r / 7, s = r % 7;
            sw[o * 57 + r] = w[o * (GOC * 7) + (icc * 8 + icl) * 7 + s];
        }
        __syncthreads();
#pragma unroll
        for (int icl = 0; icl < 8; icl++) {
            const int icg = icc * 8 + icl;
            float wv[7];
#pragma unroll
            for (int s = 0; s < 7; s++) wv[s] = sw[oc * 57 + icl * 7 + s];
#pragma unroll
            for (int m = 0; m < 7; m++) {
                const int lpl = ty + 2 * m;
                if (lpl < 13) {
                    const int base = lpl * 4;
                    float v[10];
#pragma unroll
                    for (int q = 0; q < 10; q++) v[q] = sx[icg][base + q];
#pragma unroll
                    for (int j = 0; j < 4; j++) {
                        float s = 0.f;
#pragma unroll
                        for (int q = 0; q < 7; q++) s += v[j + q] * wv[q];
                        acc[m][j] += s;
                    }
                }
            }
        }
    }
#pragma unroll
    for (int m = 0; m < 7; m++) {
        const int lpl = ty + 2 * m;
        const int lp = chunk * 13 + lpl;
        if (lpl < 13 && lp < E2P) {
            float mx = -INFINITY;
#pragma unroll
            for (int j = 0; j < 4; j++) mx = fmaxf(mx, leaky(acc[m][j]));
            g_z2[(b * E2OC + oc) * E2P + lp] = mx;
        }
    }
}

// ================= K7a: sliding sums S[b,ic,s] = sum_{l<119} z2[b,ic,l+s] =================
__global__ void k_ssum() {
    const int b = blockIdx.x, ic = threadIdx.x;
    const float* p = &g_z2[(b * E2OC + ic) * E2P];
    float s = 0.f;
    for (int t = 0; t < E3L; t++) s += p[t];
    g_S[(b * E2OC + ic) * 7 + 0] = s;
#pragma unroll
    for (int sh = 1; sh < 7; sh++) {
        s += p[E3L - 1 + sh] - p[sh - 1];
        g_S[(b * E2OC + ic) * 7 + sh] = s;
    }
}

// ================= K7b: feat[b,oc] = eb3 + (1/119)*dot(ew3[oc], S[b]) =================
__global__ void k_econv3(const float* __restrict__ w, const float* __restrict__ bb) {
    const int b = blockIdx.x, oc = threadIdx.x;
    __shared__ float sS[E2OC * 7];
    for (int i = oc; i < E2OC * 7; i += 128) sS[i] = g_S[b * (E2OC * 7) + i];
    __syncthreads();
    float a = 0.f;
    const float* wr = &w[oc * (E2OC * 7)];
    for (int i = 0; i < E2OC * 7; i++) a += sS[i] * wr[i];
    g_feat[b * E2OC + oc] = bb[oc] + a * (1.0f / 119.0f);
}

// ================= K8: classifier + log_softmax =================
__global__ void k_cls(const float* __restrict__ cw, const float* __restrict__ cb,
                      float* __restrict__ out) {
    const int b = blockIdx.x, lane = threadIdx.x;
    float p[NCLS];
#pragma unroll
    for (int c = 0; c < NCLS; c++) {
        float s = 0.f;
        for (int j = lane; j < E2OC; j += 32) s += g_feat[b * E2OC + j] * cw[c * E2OC + j];
#pragma unroll
        for (int off = 16; off; off >>= 1) s += __shfl_down_sync(0xffffffffu, s, off);
        p[c] = s;
    }
    if (lane == 0) {
        float v[NCLS], mx = -INFINITY;
#pragma unroll
        for (int c = 0; c < NCLS; c++) { v[c] = p[c] + cb[c]; mx = fmaxf(mx, v[c]); }
        float se = 0.f;
#pragma unroll
        for (int c = 0; c < NCLS; c++) se += expf(v[c] - mx);
        const float lse = mx + logf(se);
#pragma unroll
        for (int c = 0; c < NCLS; c++) out[b * NCLS + c] = v[c] - lse;
    }
}

// ================= launch =================
extern "C" void kernel_launch(void* const* d_in, const int* in_sizes, int n_in,
                              void* d_out, int out_size) {
    const float* x   = (const float*)d_in[0];
    // d_in[1] = epoch (unused in eval forward)
    const float* hw1 = (const float*)d_in[2];
    const float* hb1 = (const float*)d_in[3];
    const float* hw2 = (const float*)d_in[4];
    const float* hb2 = (const float*)d_in[5];
    const float* hw3 = (const float*)d_in[6];
    const float* hb3 = (const float*)d_in[7];
    const float* hl1 = (const float*)d_in[8];
    const float* hl2 = (const float*)d_in[9];
    const float* gw  = (const float*)d_in[10];
    const float* gb0 = (const float*)d_in[11];
    const float* ew2 = (const float*)d_in[12];
    const float* eb2 = (const float*)d_in[13];
    const float* ew3 = (const float*)d_in[14];
    const float* eb3 = (const float*)d_in[15];
    const float* cw  = (const float*)d_in[16];
    const float* cb  = (const float*)d_in[17];
    float* out = (float*)d_out;

    k_conv1<<<dim3(48, BS), 256>>>(x, hw1, hb1);
    k_conv2<<<dim3(48, BS), 256>>>(hw2, hb2);
    k_conv3<<<dim3(12, BS), 256>>>(hw3, hb3);
    k_lin1<<<dim3(4, NSPLIT), 256>>>(hl1);
    k_logits_topk<<<BS, 128>>>(hl2);
    k_gconv<<<dim3(32, BS), 256>>>(x, gw, gb0);
    k_econv2<<<dim3(10, BS), 256>>>(ew2, eb2);
    k_ssum<<<BS, 128>>>();
    k_econv3<<<BS, 128>>>(ew3, eb3);
    k_cls<<<BS, 32>>>(cw, cb, out);
}

// round 6
// speedup vs baseline: 1.1315x; 1.1315x over previous
#include <cuda_runtime.h>
#include <math.h>
#include <stdint.h>

// ---------------- problem constants ----------------
#define BS    128
#define CH    16
#define T     12288
#define C1    32
#define T1    3072
#define C2    64
#define T2    768
#define C3    8
#define LATENT 6144
#define NMW   96
#define TOPK  5
#define RED   6
#define WLEN  2048
#define GKS   15
#define GOC   64
#define LGP   508
#define E2OC  128
#define E2P   125
#define E3L   119
#define NCLS  5
#define NSPLIT 16

// ---------------- scratch ----------------
__device__ float g_h1[BS * C1 * T1];
__device__ float g_h2[BS * C2 * T2];
__device__ float g_h3[BS * LATENT];
__device__ float g_upart[NSPLIT][BS * NMW];
__device__ int   g_idx[BS * TOPK];
__device__ float g_n0[BS];
__device__ float g_z1[BS * GOC * LGP];
__device__ float g_z2[BS * E2OC * E2P];
__device__ float g_S[BS * E2OC * 7];
__device__ float g_feat[BS * E2OC];

__device__ __forceinline__ float leaky(float z) { return z >= 0.f ? z : 0.01f * z; }

// ---- packed f32x2 helpers (two independent IEEE fp32 ops per instruction) ----
typedef unsigned long long u64;
#define FMA2(d, a, b, c) \
    asm("fma.rn.f32x2 %0, %1, %2, %3;" : "=l"(d) : "l"(a), "l"(b), "l"(c))
#define ADD2(d, a, b) \
    asm("add.rn.f32x2 %0, %1, %2;" : "=l"(d) : "l"(a), "l"(b))
#define SPLAT2(d, f) \
    asm("mov.b64 %0, {%1, %1};" : "=l"(d) : "f"(f))
#define PACK2(d, lo, hi) \
    asm("mov.b64 %0, {%1, %2};" : "=l"(d) : "f"(lo), "f"(hi))
#define UNPACK2(lo, hi, v) \
    asm("mov.b64 {%0, %1}, %2;" : "=f"(lo), "=f"(hi) : "l"(v))

// ================= K1: conv1(16->32,ks7,reflect) + leaky + meanpool4, f32x2-packed ======
// Bit-exact per-output op sequence vs R1 SIMT kernel. Component h of each f32x2 lane
// handles raw-time half h*128 of the 256-raw tile. grid (48, BS), block 256 = 32oc x 8sub.
__global__ void k_conv1(const float* __restrict__ x, const float* __restrict__ w,
                        const float* __restrict__ bb) {
    const int b = blockIdx.y, tile = blockIdx.x;
    __shared__ float sw[C1 * 113];                 // per-oc stride 113 (odd)
    __shared__ __align__(8) float sx2[CH * 270];   // interleaved halves: [ic][2r+h]
    const int tid = threadIdx.x;
    for (int i = tid; i < C1 * CH * 7; i += 256) {
        int o = i / 112, r = i % 112;
        sw[o * 113 + r] = w[i];
    }
    const int t0 = tile * 256 - 3;
    for (int i = tid; i < CH * 268; i += 256) {
        int ic = i / 268, j = i % 268;
        int h = j / 134, r = j % 134;              // r fastest -> coalesced LDG
        int t = t0 + h * 128 + r;
        if (t < 0) t = -t;
        if (t >= T) t = 2 * T - 2 - t;
        sx2[ic * 270 + 2 * r + h] = x[(b * CH + ic) * T + t];
    }
    __syncthreads();
    const int o = tid & 31, sub = tid >> 5;
    const float bias = bb[o];
    u64 bias2; PACK2(bias2, bias, bias);
    u64 acc2[4][4];
#pragma unroll
    for (int pp = 0; pp < 4; pp++)
#pragma unroll
        for (int j = 0; j < 4; j++) acc2[pp][j] = bias2;
    for (int ic = 0; ic < CH; ic++) {
        u64 wr2[7];
#pragma unroll
        for (int k = 0; k < 7; k++) { float wv = sw[o * 113 + ic * 7 + k]; SPLAT2(wr2[k], wv); }
#pragma unroll
        for (int pp = 0; pp < 4; pp++) {
            const float* vb = &sx2[ic * 270 + 2 * (sub * 16 + pp * 4)];
            u64 v2[10];
#pragma unroll
            for (int m = 0; m < 10; m++) v2[m] = *(const u64*)(vb + 2 * m);
#pragma unroll
            for (int j = 0; j < 4; j++) {
                u64 s2 = 0ull;                      // (0.0f, 0.0f)
#pragma unroll
                for (int k = 0; k < 7; k++) FMA2(s2, v2[j + k], wr2[k], s2);
                ADD2(acc2[pp][j], acc2[pp][j], s2);
            }
        }
    }
#pragma unroll
    for (int pp = 0; pp < 4; pp++) {
        float m0 = 0.f, m1 = 0.f;
#pragma unroll
        for (int j = 0; j < 4; j++) {
            float a0, a1; UNPACK2(a0, a1, acc2[pp][j]);
            m0 += leaky(a0); m1 += leaky(a1);
        }
        const int q = sub * 4 + pp;
        g_h1[(b * C1 + o) * T1 + tile * 64 + q]      = m0 * 0.25f;
        g_h1[(b * C1 + o) * T1 + tile * 64 + q + 32] = m1 * 0.25f;
    }
}

// ================= K2: conv2(32->64,ks7,reflect) + leaky + meanpool4, f32x2-packed ======
// grid (48, BS): chunk = bx>>1 (128 raw), ohalf = bx&1. block 256 = 32 ocl x 8 sub.
// Component h handles raw half h*64 of the 128-raw tile. Bit-exact vs R1.
__global__ void k_conv2(const float* __restrict__ w, const float* __restrict__ bb) {
    const int b = blockIdx.y;
    const int chunk = blockIdx.x >> 1, ohalf = blockIdx.x & 1;
    __shared__ float sw[32 * 225];
    __shared__ __align__(8) float sx2[C1 * 142];
    const int tid = threadIdx.x;
    for (int i = tid; i < 32 * 32 * 7; i += 256) {
        int ol = i / 224, r = i % 224;
        sw[ol * 225 + r] = w[(ohalf * 32 + ol) * 224 + r];
    }
    const int t0 = chunk * 128 - 3;
    for (int i = tid; i < C1 * 140; i += 256) {
        int ic = i / 140, j = i % 140;
        int h = j / 70, r = j % 70;
        int t = t0 + h * 64 + r;
        if (t < 0) t = -t;
        if (t >= T1) t = 2 * T1 - 2 - t;
        sx2[ic * 142 + 2 * r + h] = g_h1[(b * C1 + ic) * T1 + t];
    }
    __syncthreads();
    const int ol = tid & 31, sub = tid >> 5;
    const int oc = ohalf * 32 + ol;
    const float bias = bb[oc];
    u64 bias2; PACK2(bias2, bias, bias);
    u64 acc2[2][4];
#pragma unroll
    for (int pp = 0; pp < 2; pp++)
#pragma unroll
        for (int j = 0; j < 4; j++) acc2[pp][j] = bias2;
    for (int ic = 0; ic < 32; ic++) {
        u64 wr2[7];
#pragma unroll
        for (int k = 0; k < 7; k++) { float wv = sw[ol * 225 + ic * 7 + k]; SPLAT2(wr2[k], wv); }
#pragma unroll
        for (int pp = 0; pp < 2; pp++) {
            const float* vb = &sx2[ic * 142 + 2 * (sub * 8 + pp * 4)];
            u64 v2[10];
#pragma unroll
            for (int m = 0; m < 10; m++) v2[m] = *(const u64*)(vb + 2 * m);
#pragma unroll
            for (int j = 0; j < 4; j++) {
                u64 s2 = 0ull;
#pragma unroll
                for (int k = 0; k < 7; k++) FMA2(s2, v2[j + k], wr2[k], s2);
                ADD2(acc2[pp][j], acc2[pp][j], s2);
            }
        }
    }
#pragma unroll
    for (int pp = 0; pp < 2; pp++) {
        float m0 = 0.f, m1 = 0.f;
#pragma unroll
        for (int j = 0; j < 4; j++) {
            float a0, a1; UNPACK2(a0, a1, acc2[pp][j]);
            m0 += leaky(a0); m1 += leaky(a1);
        }
        const int q = sub * 2 + pp;
        g_h2[(b * C2 + oc) * T2 + chunk * 32 + q]      = m0 * 0.25f;
        g_h2[(b * C2 + oc) * T2 + chunk * 32 + q + 16] = m1 * 0.25f;
    }
}

// ================= K3: conv3(64->8,ks7,reflect-same) + tanh -> flatten (verbatim R1) ====
__global__ void k_conv3(const float* __restrict__ w, const float* __restrict__ bb) {
    const int b = blockIdx.y, chunk = blockIdx.x;
    __shared__ float sw[C3 * 449];
    __shared__ float sxx[C2][70];
    const int tid = threadIdx.x;
    for (int i = tid; i < C3 * C2 * 7; i += 256) {
        int o = i / 448, r = i % 448;
        sw[o * 449 + r] = w[i];
    }
    const int t0 = chunk * 64 - 3;
    for (int i = tid; i < C2 * 70; i += 256) {
        int ic = i / 70, p = i % 70;
        int t = t0 + p;
        if (t < 0) t = -t;
        if (t >= T2) t = 2 * T2 - 2 - t;
        sxx[ic][p] = g_h2[(b * C2 + ic) * T2 + t];
    }
    __syncthreads();
    const int o = tid >> 5, tl = tid & 31;
    float a0 = bb[o], a1 = bb[o];
    for (int ic = 0; ic < C2; ic++) {
#pragma unroll
        for (int k = 0; k < 7; k++) {
            float wv = sw[o * 449 + ic * 7 + k];
            a0 += sxx[ic][tl + k] * wv;
            a1 += sxx[ic][tl + 32 + k] * wv;
        }
    }
    const int tg = chunk * 64;
    g_h3[b * LATENT + o * T2 + tg + tl]      = tanhf(a0);
    g_h3[b * LATENT + o * T2 + tg + tl + 32] = tanhf(a1);
}

// ================= K4a: u_partial = h3 @ hl1^T (NSPLIT=16; per-(b,n) d-order == R1) =====
// grid (16 btiles, 16 ds) = 256 blocks; 8 batch rows per block.
__global__ void k_lin1(const float* __restrict__ hl1) {
    const int btile = blockIdx.x, ds = blockIdx.y;
    __shared__ float sh[8 * 65];
    __shared__ float swt[96 * 65];
    const int tid = threadIdx.x;
    float acc[3];
#pragma unroll
    for (int r = 0; r < 3; r++) acc[r] = 0.f;
    const int dbase = ds * (LATENT / NSPLIT);  // 384-wide stripe, same as R1
    for (int sc = 0; sc < 6; sc++) {
        const int dd0 = dbase + sc * 64;
        __syncthreads();
        for (int i = tid; i < 8 * 64; i += 256) {
            int bl = i >> 6, d = i & 63;
            sh[bl * 65 + d] = g_h3[(btile * 8 + bl) * LATENT + dd0 + d];
        }
        for (int i = tid; i < 96 * 64; i += 256) {
            int n = i >> 6, d = i & 63;
            swt[n * 65 + d] = hl1[n * LATENT + dd0 + d];
        }
        __syncthreads();
#pragma unroll
        for (int r = 0; r < 3; r++) {
            const int p = tid + 256 * r;
            const int bl = p / 96, n = p % 96;
            float a = 0.f;
#pragma unroll 8
            for (int d = 0; d < 64; d++) a += sh[bl * 65 + d] * swt[n * 65 + d];
            acc[r] += a;
        }
    }
#pragma unroll
    for (int r = 0; r < 3; r++) {
        const int p = tid + 256 * r;
        const int bl = p / 96, n = p % 96;
        g_upart[ds][(btile * 8 + bl) * 96 + n] = acc[r];
    }
}

// ================= K4b: u-reduce + leaky + @hl2^T + top-k (verbatim R1) =================
__global__ void k_logits_topk(const float* __restrict__ hl2) {
    const int b = blockIdx.x, tid = threadIdx.x;
    __shared__ float su[96];
    __shared__ float slog[96];
    if (tid < 96) {
        float u = 0.f;
#pragma unroll
        for (int ds = 0; ds < NSPLIT; ds++) u += g_upart[ds][b * 96 + tid];
        su[tid] = leaky(u);
    }
    __syncthreads();
    if (tid < 96) {
        float lg = 0.f;
        for (int n = 0; n < 96; n++) lg += su[n] * hl2[tid * 96 + n];
        slog[tid] = lg;
    }
    __syncthreads();
    if (tid == 0) {
        int n0 = 0;
        for (int k = 0; k < TOPK; k++) {
            float best = -INFINITY;
            int bi = 0;
            for (int n = 0; n < 96; n++) {
                if (slog[n] > best) { best = slog[n]; bi = n; }
            }
            slog[bi] = -INFINITY;
            g_idx[b * TOPK + k] = bi;
            if (bi / RED == 0) n0++;
        }
        g_n0[b] = (float)n0;
    }
}

// ================= K5: grouped conv (verbatim R1) =================
__global__ void k_gconv(const float* __restrict__ x, const float* __restrict__ gw,
                        const float* __restrict__ gb0) {
    const int b = blockIdx.y, chunk = blockIdx.x;
    __shared__ float sgw[TOPK * GOC * GKS];
    __shared__ float sxw[TOPK][80];
    __shared__ int sidx[TOPK];
    const int tid = threadIdx.x;
    if (tid < TOPK) sidx[tid] = g_idx[b * TOPK + tid];
    __syncthreads();
    for (int i = tid; i < TOPK * GOC * GKS; i += 256) {
        int k = i / (GOC * GKS), r = i % (GOC * GKS);
        sgw[i] = gw[(sidx[k] / RED) * (GOC * GKS) + r];
    }
    for (int i = tid; i < TOPK * 80; i += 256) {
        int k = i / 80, p = i % 80;
        int pos = chunk * 64 + p;
        float v = 0.f;
        if (pos < WLEN) v = x[b * (CH * T) + sidx[k] * WLEN + pos];
        sxw[k][p] = v;
    }
    __syncthreads();
    const int o = tid & 63, ty = tid >> 6;
    const float biasv = g_n0[b] * gb0[o];
#pragma unroll
    for (int rep = 0; rep < 4; rep++) {
        const int lpl = ty + 4 * rep;
        const int lp = chunk * 16 + lpl;
        float accj[4];
#pragma unroll
        for (int j = 0; j < 4; j++) accj[j] = biasv;
        for (int k = 0; k < TOPK; k++) {
            float wv[GKS];
#pragma unroll
            for (int s = 0; s < GKS; s++) wv[s] = sgw[k * (GOC * GKS) + o * GKS + s];
            const int r0 = lpl * 4;
            float v[18];
#pragma unroll
            for (int m = 0; m < 18; m++) v[m] = sxw[k][r0 + m];
#pragma unroll
            for (int j = 0; j < 4; j++) {
                float s = 0.f;
#pragma unroll
                for (int q = 0; q < GKS; q++) s += v[j + q] * wv[q];
                accj[j] += s;
            }
        }
        if (lp < LGP) {
            float mx = -INFINITY;
#pragma unroll
            for (int j = 0; j < 4; j++) mx = fmaxf(mx, leaky(accj[j]));
            g_z1[(b * GOC + o) * LGP + lp] = mx;
        }
    }
}

// ================= K6: ew2 conv(64->128,ks7) + leaky + maxpool4, f32x2 oc-paired ========
// grid (10, BS), block 256 = 64 ocpairs x 4 ty. Pair = (oc, oc+64); weights staged as
// interleaved b64 pairs (zero pack cost); multiplicand splatted (alu pipe, overlapped).
__global__ void k_econv2(const float* __restrict__ w, const float* __restrict__ bb) {
    const int b = blockIdx.y, chunk = blockIdx.x;
    __shared__ __align__(8) float swp[64 * 57 * 2];   // [op][r<56 pad57] b64 pairs
    __shared__ float sxe[GOC][58];
    const int tid = threadIdx.x;
    const int rbase = chunk * 52;
    for (int i = tid; i < GOC * 58; i += 256) {
        int ic = i / 58, p = i % 58;
        int idx = rbase + p;
        sxe[ic][p] = (idx < LGP) ? g_z1[(b * GOC + ic) * LGP + idx] : 0.f;
    }
    const int op = tid & 63, ty = tid >> 6;
    u64 acc2[4][4];
    {
        u64 bias2; PACK2(bias2, bb[op], bb[op + 64]);
#pragma unroll
        for (int i = 0; i < 4; i++)
#pragma unroll
            for (int j = 0; j < 4; j++) acc2[i][j] = bias2;
    }
    for (int icc = 0; icc < 8; icc++) {
        __syncthreads();
        for (int i = tid; i < 64 * 56; i += 256) {
            int o = i / 56, r = i % 56;
            swp[(o * 57 + r) * 2]     = w[o * (GOC * 7) + icc * 56 + r];
            swp[(o * 57 + r) * 2 + 1] = w[(o + 64) * (GOC * 7) + icc * 56 + r];
        }
        __syncthreads();
#pragma unroll
        for (int icl = 0; icl < 8; icl++) {
            const int icg = icc * 8 + icl;
            u64 wv2[7];
#pragma unroll
            for (int s = 0; s < 7; s++)
                wv2[s] = *(const u64*)&swp[(op * 57 + icl * 7 + s) * 2];
#pragma unroll
            for (int i = 0; i < 4; i++) {
                const int m = ty + 4 * i;
                if (m < 13) {
                    const int base = m * 4;
                    u64 v2[10];
#pragma unroll
                    for (int q = 0; q < 10; q++) { float vv = sxe[icg][base + q]; SPLAT2(v2[q], vv); }
#pragma unroll
                    for (int j = 0; j < 4; j++) {
                        u64 s2 = 0ull;
#pragma unroll
                        for (int q = 0; q < 7; q++) FMA2(s2, v2[j + q], wv2[q], s2);
                        ADD2(acc2[i][j], acc2[i][j], s2);
                    }
                }
            }
        }
    }
#pragma unroll
    for (int i = 0; i < 4; i++) {
        const int m = ty + 4 * i;
        const int lp = chunk * 13 + m;
        if (m < 13 && lp < E2P) {
            float mx0 = -INFINITY, mx1 = -INFINITY;
#pragma unroll
            for (int j = 0; j < 4; j++) {
                float a0, a1; UNPACK2(a0, a1, acc2[i][j]);
                mx0 = fmaxf(mx0, leaky(a0));
                mx1 = fmaxf(mx1, leaky(a1));
            }
            g_z2[(b * E2OC + op) * E2P + lp]        = mx0;
            g_z2[(b * E2OC + op + 64) * E2P + lp]   = mx1;
        }
    }
}

// ================= K7a: sliding sums (verbatim R1) =================
__global__ void k_ssum() {
    const int b = blockIdx.x, ic = threadIdx.x;
    const float* p = &g_z2[(b * E2OC + ic) * E2P];
    float s = 0.f;
    for (int t = 0; t < E3L; t++) s += p[t];
    g_S[(b * E2OC + ic) * 7 + 0] = s;
#pragma unroll
    for (int sh = 1; sh < 7; sh++) {
        s += p[E3L - 1 + sh] - p[sh - 1];
        g_S[(b * E2OC + ic) * 7 + sh] = s;
    }
}

// ================= K7b: feat = eb3 + (1/119)*dot(ew3, S) (verbatim R1) =================
__global__ void k_econv3(const float* __restrict__ w, const float* __restrict__ bb) {
    const int b = blockIdx.x, oc = threadIdx.x;
    __shared__ float sS[E2OC * 7];
    for (int i = oc; i < E2OC * 7; i += 128) sS[i] = g_S[b * (E2OC * 7) + i];
    __syncthreads();
    float a = 0.f;
    const float* wr = &w[oc * (E2OC * 7)];
    for (int i = 0; i < E2OC * 7; i++) a += sS[i] * wr[i];
    g_feat[b * E2OC + oc] = bb[oc] + a * (1.0f / 119.0f);
}

// ================= K8: classifier + log_softmax (verbatim R1) =================
__global__ void k_cls(const float* __restrict__ cw, const float* __restrict__ cb,
                      float* __restrict__ out) {
    const int b = blockIdx.x, lane = threadIdx.x;
    float p[NCLS];
#pragma unroll
    for (int c = 0; c < NCLS; c++) {
        float s = 0.f;
        for (int j = lane; j < E2OC; j += 32) s += g_feat[b * E2OC + j] * cw[c * E2OC + j];
#pragma unroll
        for (int off = 16; off; off >>= 1) s += __shfl_down_sync(0xffffffffu, s, off);
        p[c] = s;
    }
    if (lane == 0) {
        float v[NCLS], mx = -INFINITY;
#pragma unroll
        for (int c = 0; c < NCLS; c++) { v[c] = p[c] + cb[c]; mx = fmaxf(mx, v[c]); }
        float se = 0.f;
#pragma unroll
        for (int c = 0; c < NCLS; c++) se += expf(v[c] - mx);
        const float lse = mx + logf(se);
#pragma unroll
        for (int c = 0; c < NCLS; c++) out[b * NCLS + c] = v[c] - lse;
    }
}

// ================= launch =================
extern "C" void kernel_launch(void* const* d_in, const int* in_sizes, int n_in,
                              void* d_out, int out_size) {
    const float* x   = (const float*)d_in[0];
    const float* hw1 = (const float*)d_in[2];
    const float* hb1 = (const float*)d_in[3];
    const float* hw2 = (const float*)d_in[4];
    const float* hb2 = (const float*)d_in[5];
    const float* hw3 = (const float*)d_in[6];
    const float* hb3 = (const float*)d_in[7];
    const float* hl1 = (const float*)d_in[8];
    const float* hl2 = (const float*)d_in[9];
    const float* gw  = (const float*)d_in[10];
    const float* gb0 = (const float*)d_in[11];
    const float* ew2 = (const float*)d_in[12];
    const float* eb2 = (const float*)d_in[13];
    const float* ew3 = (const float*)d_in[14];
    const float* eb3 = (const float*)d_in[15];
    const float* cw  = (const float*)d_in[16];
    const float* cb  = (const float*)d_in[17];
    float* out = (float*)d_out;

    k_conv1<<<dim3(48, BS), 256>>>(x, hw1, hb1);
    k_conv2<<<dim3(48, BS), 256>>>(hw2, hb2);
    k_conv3<<<dim3(12, BS), 256>>>(hw3, hb3);
    k_lin1<<<dim3(16, NSPLIT), 256>>>(hl1);
    k_logits_topk<<<BS, 128>>>(hl2);
    k_gconv<<<dim3(32, BS), 256>>>(x, gw, gb0);
    k_econv2<<<dim3(10, BS), 256>>>(ew2, eb2);
    k_ssum<<<BS, 128>>>();
    k_econv3<<<BS, 128>>>(ew3, eb3);
    k_cls<<<BS, 32>>>(cw, cb, out);
}